// round 1
// baseline (speedup 1.0000x reference)
#include <cuda_runtime.h>

// SplitWin_Normalize: 3-stage split-window normalization along the strided
// (bin) axis of a (4096 bins, 4096 lines) fp32 array, lines contiguous.
//
// Numerical strategy: replicate the reference's arithmetic exactly —
// box filters as fp32 *sequential* cumsum differences over the
// symmetric-padded column (starting from bin 0, full column, so cs
// magnitudes and rounding paths match), IEEE round-to-nearest divisions
// (__fdiv_rn), (a+b)*0.5 for /2 (bitwise-exact). This minimizes
// where()-branch flips, which dominate the error budget.

static const int NB = 4096;           // bins (filter axis; memory stride NL)
static const int NL = 4096;           // lines (contiguous axis)
static const int CS_MAX = NB + 41;    // cs length for w=41 (pad=20): NB+2*20+1

// Scratch (allocation-free rule: __device__ globals).
__device__ float g_cs[CS_MAX * NL];   // padded cumsum, [m][line]
__device__ float g_c [NB * NL];       // "clipped" intermediate, [bin][line]

// ---------------------------------------------------------------------------
// Serial per-line cumsum of the symmetric-padded column.
//   xp[k] = x[pad-1-k]        for k <  pad          (numpy 'symmetric' left)
//   xp[k] = x[k-pad]          for pad <= k < NB+pad
//   xp[k] = x[2*NB+pad-1-k]   for k >= NB+pad       (right)
//   cs[0] = 0; cs[m] = cs[m-1] + xp[m-1]   (sequential fp32, matches jnp.cumsum path)
// One thread per line; coalesced LDG/STG across the warp.
// ---------------------------------------------------------------------------
template <bool SRC_IS_GC>
__global__ void cumsum_pad_kernel(const float* __restrict__ xsrc, int pad)
{
    const float* src = SRC_IS_GC ? (const float*)g_c : xsrc;
    int l = blockIdx.x * blockDim.x + threadIdx.x;   // line index, grid sized exactly

    float c = 0.0f;
    g_cs[l] = 0.0f;                                  // cs[0]

    // left reflect pad
    #pragma unroll 1
    for (int k = 0; k < pad; ++k) {
        c += src[(pad - 1 - k) * NL + l];
        g_cs[(k + 1) * NL + l] = c;
    }
    // main body — loads are independent of the accumulator chain; unroll for MLP
    #pragma unroll 8
    for (int k = 0; k < NB; ++k) {
        c += src[k * NL + l];
        g_cs[(pad + 1 + k) * NL + l] = c;
    }
    // right reflect pad
    #pragma unroll 1
    for (int k = 0; k < pad; ++k) {
        c += src[(NB - 1 - k) * NL + l];
        g_cs[(NB + pad + 1 + k) * NL + l] = c;
    }
}

// ---------------------------------------------------------------------------
// Clip stage (winsz=41, gap=20):
//   filtered[j] = (cs[j+41] - cs[j]) / 41            (IEEE div, like reference)
//   fwd(i) = i+41 if < NB else 2*NB-43-i
//   aft(i) = 41-i if i <= 41 else i-42
//   smoothed = (filtered[fwd] + filtered[aft]) * 0.5
//   out = (x > clip*smoothed) ? smoothed : x         (replace = 1)
// Always writes g_c. One thread = 4 lines at one bin (float4, coalesced).
// ---------------------------------------------------------------------------
template <bool SRC_IS_GC>
__global__ void clip_kernel(const float* __restrict__ xsrc, float clip)
{
    const float* xin = SRC_IS_GC ? (const float*)g_c : xsrc;

    int i  = blockIdx.y;                                   // bin
    int l4 = blockIdx.x * blockDim.x + threadIdx.x;        // float4 index in line dim
    const int LD4 = NL / 4;

    int fwd = (i + 41 < NB) ? (i + 41) : (2 * NB - 43 - i);
    int aft = (i <= 41) ? (41 - i) : (i - 42);

    const float4* cs4 = (const float4*)g_cs;
    float4 fa = cs4[(fwd + 41) * LD4 + l4];
    float4 fb = cs4[ fwd       * LD4 + l4];
    float4 ga = cs4[(aft + 41) * LD4 + l4];
    float4 gb = cs4[ aft       * LD4 + l4];
    float4 xv = ((const float4*)xin)[i * LD4 + l4];

    float4 r;
    {
        float ff = __fdiv_rn(fa.x - fb.x, 41.0f);
        float fg = __fdiv_rn(ga.x - gb.x, 41.0f);
        float sm = (ff + fg) * 0.5f;
        r.x = (xv.x > clip * sm) ? sm : xv.x;
    }
    {
        float ff = __fdiv_rn(fa.y - fb.y, 41.0f);
        float fg = __fdiv_rn(ga.y - gb.y, 41.0f);
        float sm = (ff + fg) * 0.5f;
        r.y = (xv.y > clip * sm) ? sm : xv.y;
    }
    {
        float ff = __fdiv_rn(fa.z - fb.z, 41.0f);
        float fg = __fdiv_rn(ga.z - gb.z, 41.0f);
        float sm = (ff + fg) * 0.5f;
        r.z = (xv.z > clip * sm) ? sm : xv.z;
    }
    {
        float ff = __fdiv_rn(fa.w - fb.w, 41.0f);
        float fg = __fdiv_rn(ga.w - gb.w, 41.0f);
        float sm = (ff + fg) * 0.5f;
        r.w = (xv.w > clip * sm) ? sm : xv.w;
    }
    ((float4*)g_c)[i * LD4 + l4] = r;
}

// ---------------------------------------------------------------------------
// Final stage: clipped3 = (cs[i+25]-cs[i])/25 (winsz=25, gap=0, pad=12),
// out = x / clipped3 (IEEE divs, matching reference order of operations).
// ---------------------------------------------------------------------------
__global__ void final_kernel(const float* __restrict__ xin, float* __restrict__ out)
{
    int i  = blockIdx.y;
    int l4 = blockIdx.x * blockDim.x + threadIdx.x;
    const int LD4 = NL / 4;

    const float4* cs4 = (const float4*)g_cs;
    float4 a  = cs4[(i + 25) * LD4 + l4];
    float4 b  = cs4[ i        * LD4 + l4];
    float4 xv = ((const float4*)xin)[i * LD4 + l4];

    float4 r;
    r.x = __fdiv_rn(xv.x, __fdiv_rn(a.x - b.x, 25.0f));
    r.y = __fdiv_rn(xv.y, __fdiv_rn(a.y - b.y, 25.0f));
    r.z = __fdiv_rn(xv.z, __fdiv_rn(a.z - b.z, 25.0f));
    r.w = __fdiv_rn(xv.w, __fdiv_rn(a.w - b.w, 25.0f));
    ((float4*)out)[i * LD4 + l4] = r;
}

// ---------------------------------------------------------------------------
extern "C" void kernel_launch(void* const* d_in, const int* in_sizes, int n_in,
                              void* d_out, int out_size)
{
    const float* x  = (const float*)d_in[0];   // (1, 4096, 4096) fp32, [bin][line]
    float* out      = (float*)d_out;

    dim3 blkE(256);
    dim3 grdE(NL / 4 / 256, NB);               // (4, 4096)
    dim3 blkS(32);
    dim3 grdS(NL / 32);                        // 128 blocks x 32 threads = 4096 lines

    // Stage 1: winsz=41 gap=20 clip=3
    cumsum_pad_kernel<false><<<grdS, blkS>>>(x, 20);
    clip_kernel<false><<<grdE, blkE>>>(x, 3.0f);

    // Stage 2: winsz=41 gap=20 clip=2  (in-place on g_c; purely elementwise in x)
    cumsum_pad_kernel<true><<<grdS, blkS>>>(nullptr, 20);
    clip_kernel<true><<<grdE, blkE>>>(nullptr, 2.0f);

    // Stage 3: winsz=25 gap=0 -> clipped = filtered; then out = x / clipped
    cumsum_pad_kernel<true><<<grdS, blkS>>>(nullptr, 12);
    final_kernel<<<grdE, blkE>>>(x, out);
}

// round 2
// speedup vs baseline: 8.3931x; 8.3931x over previous
#include <cuda_runtime.h>

// SplitWin_Normalize: 3-stage split-window normalization along the strided
// (bin) axis of a (4096 bins, 4096 lines) fp32 array, lines contiguous.
//
// R2: replace the serial per-line cumsum (128 warps total, latency-bound,
// ~1300us each) with a chunked blocked-sequential scan: chunk-sum kernel +
// scan/write kernel, both with 135k threads. cs values deviate from pure
// sequential by a few ulp(2048) -- same scale as the already-passing
// sequential-vs-reference mismatch.

static const int NB = 4096;           // bins (filter axis; memory stride NL)
static const int NL = 4096;           // lines (contiguous axis)
static const int CS_MAX = NB + 41;    // cs length for w=41 (pad=20): NB+2*20+1
static const int CHUNK = 128;         // padded elements per scan chunk
static const int NCH_MAX = (NB + 40 + CHUNK - 1) / CHUNK;  // 33

// Scratch (allocation-free rule: __device__ globals).
__device__ float g_cs[CS_MAX * NL];        // padded cumsum, [m][line]
__device__ float g_c [NB * NL];            // "clipped" intermediate, [bin][line]
__device__ float g_csum[NCH_MAX * NL];     // per-chunk sums, [chunk][line]

// padded index m -> source bin row (numpy 'symmetric' reflect)
__device__ __forceinline__ int pad_row(int m, int pad)
{
    if (m < pad)      return pad - 1 - m;
    if (m < NB + pad) return m - pad;
    return 2 * NB + pad - 1 - m;
}

// ---------------------------------------------------------------------------
// Kernel A: per-(line, chunk) sum of CHUNK padded elements.
// blockIdx.y = chunk, blockIdx.x*blockDim.x+threadIdx.x = line (coalesced).
// ---------------------------------------------------------------------------
template <bool SRC_IS_GC>
__global__ void chunksum_kernel(const float* __restrict__ xsrc, int pad, int P)
{
    const float* src = SRC_IS_GC ? (const float*)g_c : xsrc;
    int l = blockIdx.x * blockDim.x + threadIdx.x;
    int c = blockIdx.y;

    int m0 = c * CHUNK;
    int mend = min(m0 + CHUNK, P);

    float s = 0.0f;
    #pragma unroll 4
    for (int m = m0; m < mend; ++m)
        s += src[pad_row(m, pad) * NL + l];

    g_csum[c * NL + l] = s;
}

// ---------------------------------------------------------------------------
// Kernel C: per-(line, chunk): offset = sequential sum of preceding chunk
// sums (L2-resident, coalesced across lines), then local sequential cumsum
// written to g_cs. cs[0] = 0 written by chunk 0.
// ---------------------------------------------------------------------------
template <bool SRC_IS_GC>
__global__ void scanwrite_kernel(const float* __restrict__ xsrc, int pad, int P)
{
    const float* src = SRC_IS_GC ? (const float*)g_c : xsrc;
    int l = blockIdx.x * blockDim.x + threadIdx.x;
    int c = blockIdx.y;

    float off = 0.0f;
    for (int j = 0; j < c; ++j)
        off += g_csum[j * NL + l];

    if (c == 0)
        g_cs[l] = 0.0f;

    int m0 = c * CHUNK;
    int mend = min(m0 + CHUNK, P);

    float acc = 0.0f;
    #pragma unroll 4
    for (int m = m0; m < mend; ++m) {
        acc += src[pad_row(m, pad) * NL + l];
        g_cs[(m + 1) * NL + l] = off + acc;
    }
}

// ---------------------------------------------------------------------------
// Clip stage (winsz=41, gap=20):
//   filtered[j] = (cs[j+41] - cs[j]) / 41            (IEEE div, like reference)
//   fwd(i) = i+41 if < NB else 2*NB-43-i
//   aft(i) = 41-i if i <= 41 else i-42
//   smoothed = (filtered[fwd] + filtered[aft]) * 0.5
//   out = (x > clip*smoothed) ? smoothed : x         (replace = 1)
// Always writes g_c. One thread = 4 lines at one bin (float4, coalesced).
// ---------------------------------------------------------------------------
template <bool SRC_IS_GC>
__global__ void clip_kernel(const float* __restrict__ xsrc, float clip)
{
    const float* xin = SRC_IS_GC ? (const float*)g_c : xsrc;

    int i  = blockIdx.y;                                   // bin
    int l4 = blockIdx.x * blockDim.x + threadIdx.x;        // float4 index in line dim
    const int LD4 = NL / 4;

    int fwd = (i + 41 < NB) ? (i + 41) : (2 * NB - 43 - i);
    int aft = (i <= 41) ? (41 - i) : (i - 42);

    const float4* cs4 = (const float4*)g_cs;
    float4 fa = cs4[(fwd + 41) * LD4 + l4];
    float4 fb = cs4[ fwd       * LD4 + l4];
    float4 ga = cs4[(aft + 41) * LD4 + l4];
    float4 gb = cs4[ aft       * LD4 + l4];
    float4 xv = ((const float4*)xin)[i * LD4 + l4];

    float4 r;
    {
        float ff = __fdiv_rn(fa.x - fb.x, 41.0f);
        float fg = __fdiv_rn(ga.x - gb.x, 41.0f);
        float sm = (ff + fg) * 0.5f;
        r.x = (xv.x > clip * sm) ? sm : xv.x;
    }
    {
        float ff = __fdiv_rn(fa.y - fb.y, 41.0f);
        float fg = __fdiv_rn(ga.y - gb.y, 41.0f);
        float sm = (ff + fg) * 0.5f;
        r.y = (xv.y > clip * sm) ? sm : xv.y;
    }
    {
        float ff = __fdiv_rn(fa.z - fb.z, 41.0f);
        float fg = __fdiv_rn(ga.z - gb.z, 41.0f);
        float sm = (ff + fg) * 0.5f;
        r.z = (xv.z > clip * sm) ? sm : xv.z;
    }
    {
        float ff = __fdiv_rn(fa.w - fb.w, 41.0f);
        float fg = __fdiv_rn(ga.w - gb.w, 41.0f);
        float sm = (ff + fg) * 0.5f;
        r.w = (xv.w > clip * sm) ? sm : xv.w;
    }
    ((float4*)g_c)[i * LD4 + l4] = r;
}

// ---------------------------------------------------------------------------
// Final stage: clipped3 = (cs[i+25]-cs[i])/25 (winsz=25, gap=0, pad=12),
// out = x / clipped3 (IEEE divs, matching reference order of operations).
// ---------------------------------------------------------------------------
__global__ void final_kernel(const float* __restrict__ xin, float* __restrict__ out)
{
    int i  = blockIdx.y;
    int l4 = blockIdx.x * blockDim.x + threadIdx.x;
    const int LD4 = NL / 4;

    const float4* cs4 = (const float4*)g_cs;
    float4 a  = cs4[(i + 25) * LD4 + l4];
    float4 b  = cs4[ i        * LD4 + l4];
    float4 xv = ((const float4*)xin)[i * LD4 + l4];

    float4 r;
    r.x = __fdiv_rn(xv.x, __fdiv_rn(a.x - b.x, 25.0f));
    r.y = __fdiv_rn(xv.y, __fdiv_rn(a.y - b.y, 25.0f));
    r.z = __fdiv_rn(xv.z, __fdiv_rn(a.z - b.z, 25.0f));
    r.w = __fdiv_rn(xv.w, __fdiv_rn(a.w - b.w, 25.0f));
    ((float4*)out)[i * LD4 + l4] = r;
}

// ---------------------------------------------------------------------------
extern "C" void kernel_launch(void* const* d_in, const int* in_sizes, int n_in,
                              void* d_out, int out_size)
{
    const float* x  = (const float*)d_in[0];   // (1, 4096, 4096) fp32, [bin][line]
    float* out      = (float*)d_out;

    dim3 blkE(256);
    dim3 grdE(NL / 4 / 256, NB);               // (4, 4096)

    // scan kernels: grid (line-groups, chunks)
    const int P41 = NB + 40;                   // padded length, pad=20
    const int P25 = NB + 24;                   // padded length, pad=12
    const int NCH41 = (P41 + CHUNK - 1) / CHUNK;   // 33
    const int NCH25 = (P25 + CHUNK - 1) / CHUNK;   // 33
    dim3 blkS(256);
    dim3 grdS41(NL / 256, NCH41);
    dim3 grdS25(NL / 256, NCH25);

    // Stage 1: winsz=41 gap=20 clip=3
    chunksum_kernel<false><<<grdS41, blkS>>>(x, 20, P41);
    scanwrite_kernel<false><<<grdS41, blkS>>>(x, 20, P41);
    clip_kernel<false><<<grdE, blkE>>>(x, 3.0f);

    // Stage 2: winsz=41 gap=20 clip=2  (reads/writes g_c; elementwise in x)
    chunksum_kernel<true><<<grdS41, blkS>>>(nullptr, 20, P41);
    scanwrite_kernel<true><<<grdS41, blkS>>>(nullptr, 20, P41);
    clip_kernel<true><<<grdE, blkE>>>(nullptr, 2.0f);

    // Stage 3: winsz=25 gap=0 -> clipped = filtered; then out = x / clipped
    chunksum_kernel<true><<<grdS25, blkS>>>(nullptr, 12, P25);
    scanwrite_kernel<true><<<grdS25, blkS>>>(nullptr, 12, P25);
    final_kernel<<<grdE, blkE>>>(x, out);
}

// round 3
// speedup vs baseline: 15.1732x; 1.8078x over previous
#include <cuda_runtime.h>

// SplitWin_Normalize, R3: fully fused per-stage sliding-window kernels.
// Each stage (winsz=41, gap=20) = one streaming kernel (interior bins,
// running window sums for filtered[i+41] and filtered[i-42]) + one tiny
// brute-force kernel for the 83 edge bins where the reflected fwd/aft
// indices are non-monotone. Stage 3 (winsz=25, gap=0) fuses the filter
// with the final x/filtered divide. No cumsum arrays, no gather pass:
// 134 MB DRAM per stage instead of ~400 MB.
//
// Input layout: (1, 4096 bins, 4096 lines), lines contiguous. Filter axis
// = bins (stride NL). One thread per line per bin-tile; coalesced.

static const int NB = 4096;     // bins (filter axis)
static const int NL = 4096;     // lines (contiguous)
static const int TB = 64;       // bins per thread (streaming tile)

// Scratch (__device__ globals per allocation rules).
__device__ float g_c1[NB * NL];   // stage-1 clipped
__device__ float g_c2[NB * NL];   // stage-2 clipped

// numpy 'symmetric' reflect for p in [-63, NB+62]
__device__ __forceinline__ int refl(int p)
{
    if (p < 0)   return -1 - p;
    if (p >= NB) return 2 * NB - 1 - p;
    return p;
}

// ---------------------------------------------------------------------------
// Interior streaming kernel for stages 1/2 (w=41, gap=20).
//   filtered[m]  = mean(src[m-20 .. m+20])  (symmetric-reflect padded)
//   fwd(i)=i+41, aft(i)=i-42  (monotone for i in [42, NB-42])
//   W_fwd(i) = sum src[i+21 .. i+61],  W_aft(i) = sum src[i-62 .. i-22]
//   smoothed = (W_fwd + W_aft) / 82
//   dst[i] = (src[i] > clip*smoothed) ? smoothed : src[i]
// Grid: (NL/256 line-groups, NB/TB bin-tiles), 256 threads = 256 lines.
// ---------------------------------------------------------------------------
__global__ void stage_stream_kernel(const float* __restrict__ src,
                                    float* __restrict__ dst, float clip)
{
    const int l  = blockIdx.x * blockDim.x + threadIdx.x;
    const int t0 = blockIdx.y * TB;
    const float SC = 0.5f / 41.0f;

    int i0 = (t0 < 42) ? 42 : t0;
    int i1 = t0 + TB - 1;
    if (i1 > NB - 42) i1 = NB - 42;
    if (i0 > i1) return;

    // init running windows at i0
    float Wf = 0.0f, Wa = 0.0f;
    #pragma unroll 1
    for (int k = 21; k <= 61; ++k) Wf += src[refl(i0 + k) * NL + l];
    #pragma unroll 1
    for (int k = 22; k <= 62; ++k) Wa += src[refl(i0 - k) * NL + l];

    #pragma unroll 1
    for (int i = i0;;) {
        float sm = (Wf + Wa) * SC;
        float xv = src[i * NL + l];
        dst[i * NL + l] = (xv > clip * sm) ? sm : xv;
        if (++i > i1) break;
        Wf += src[refl(i + 61) * NL + l] - src[refl(i + 20) * NL + l];
        Wa += src[refl(i - 22) * NL + l] - src[refl(i - 63) * NL + l];
    }
}

// ---------------------------------------------------------------------------
// Edge bins for stages 1/2: i in [0,42) and (NB-42, NB-1]; 83 bins total.
// Brute-force 41-element window sums at the reflected fwd/aft positions.
// Grid: (NL/256, 83). Fully parallel; removes stragglers from streaming grid.
// ---------------------------------------------------------------------------
__global__ void stage_edge_kernel(const float* __restrict__ src,
                                  float* __restrict__ dst, float clip)
{
    const int l = blockIdx.x * blockDim.x + threadIdx.x;
    const int j = blockIdx.y;                       // 0..82
    const int i = (j < 42) ? j : (NB - 41 + (j - 42));
    const float SC = 0.5f / 41.0f;

    const int f = (i + 41 < NB) ? (i + 41) : (2 * NB - 43 - i);
    const int a = (i <= 41) ? (41 - i) : (i - 42);

    float sf = 0.0f, sa = 0.0f;
    #pragma unroll 1
    for (int k = -20; k <= 20; ++k) {
        sf += src[refl(f + k) * NL + l];
        sa += src[refl(a + k) * NL + l];
    }
    float sm = (sf + sa) * SC;
    float xv = src[i * NL + l];
    dst[i * NL + l] = (xv > clip * sm) ? sm : xv;
}

// ---------------------------------------------------------------------------
// Stage 3 (w=25, gap=0) fused with final divide:
//   clipped3[i] = mean(c2[i-12 .. i+12]);  out[i] = x[i] / clipped3[i]
// Single monotone stream, reflect handles edges inline.
// ---------------------------------------------------------------------------
__global__ void stage3_kernel(const float* __restrict__ c2,
                              const float* __restrict__ x,
                              float* __restrict__ out)
{
    const int l  = blockIdx.x * blockDim.x + threadIdx.x;
    const int t0 = blockIdx.y * TB;
    const int i1 = t0 + TB - 1;
    const float R25 = 1.0f / 25.0f;

    float W = 0.0f;
    #pragma unroll 1
    for (int k = -12; k <= 12; ++k) W += c2[refl(t0 + k) * NL + l];

    #pragma unroll 1
    for (int i = t0;;) {
        float f = W * R25;
        out[i * NL + l] = __fdiv_rn(x[i * NL + l], f);
        if (++i > i1) break;
        W += c2[refl(i + 12) * NL + l] - c2[refl(i - 13) * NL + l];
    }
}

// ---------------------------------------------------------------------------
extern "C" void kernel_launch(void* const* d_in, const int* in_sizes, int n_in,
                              void* d_out, int out_size)
{
    const float* x = (const float*)d_in[0];   // [bin][line] fp32
    float* out     = (float*)d_out;

    float* c1 = nullptr, *c2 = nullptr;
    cudaGetSymbolAddress((void**)&c1, g_c1);
    cudaGetSymbolAddress((void**)&c2, g_c2);

    dim3 blk(256);
    dim3 grdMain(NL / 256, NB / TB);   // (16, 64)
    dim3 grdEdge(NL / 256, 83);        // (16, 83)

    // Stage 1: x -> c1   (clip=3)
    stage_stream_kernel<<<grdMain, blk>>>(x, c1, 3.0f);
    stage_edge_kernel  <<<grdEdge, blk>>>(x, c1, 3.0f);

    // Stage 2: c1 -> c2  (clip=2)
    stage_stream_kernel<<<grdMain, blk>>>(c1, c2, 2.0f);
    stage_edge_kernel  <<<grdEdge, blk>>>(c1, c2, 2.0f);

    // Stage 3 + final divide: out = x / boxfilter25(c2)
    stage3_kernel<<<grdMain, blk>>>(c2, x, out);
}